// round 1
// baseline (speedup 1.0000x reference)
#include <cuda_runtime.h>
#include <cstdint>

#define BB 8
#define CC 256
#define OO 256
#define HH 64
#define WW 64
#define DGRP 4
#define CG 64
#define KK2 9
#define CK 2304      /* C*K2 */
#define HWP 4096     /* H*W */

// ---------------- scratch (device globals; no cudaMalloc allowed) ----------------
__device__ float g_xT[(size_t)BB * DGRP * HWP * CG];   // 32 MB, NHWC-per-group
__device__ float g_col[(size_t)BB * HWP * CK];         // 302 MB, im2col buffer
__device__ float g_wT[(size_t)CK * OO];                // 2.36 MB, permuted weights
__device__ float g_y[(size_t)BB * HWP * OO];           // 32 MB, conv out (NHWC)

// ---------------- f32x2 packed helpers ----------------
__device__ __forceinline__ unsigned long long pack2(float v) {
    unsigned long long r;
    unsigned u = __float_as_uint(v);
    asm("mov.b64 %0, {%1, %2};" : "=l"(r) : "r"(u), "r"(u));
    return r;
}
__device__ __forceinline__ void fma2(unsigned long long& d, unsigned long long a,
                                     unsigned long long b) {
    asm("fma.rn.f32x2 %0, %1, %2, %0;" : "+l"(d) : "l"(a), "l"(b));
}
__device__ __forceinline__ void unpack2(unsigned long long v, float& lo, float& hi) {
    unsigned a, b;
    asm("mov.b64 {%0, %1}, %2;" : "=r"(a), "=r"(b) : "l"(v));
    lo = __uint_as_float(a);
    hi = __uint_as_float(b);
}

// ---------------- kernel 1: permute weights to wT[ck][o], ck=(g,k2,cg) ----------------
__global__ void wprep_kernel(const float* __restrict__ wd) {
    int idx = blockIdx.x * 256 + threadIdx.x;   // < CK*OO = 589824
    int o = idx & 255;
    int ck = idx >> 8;
    int cg = ck & 63;
    int t = ck >> 6;
    int k2 = t % KK2;
    int g = t / KK2;
    int c = g * CG + cg;
    g_wT[idx] = wd[((size_t)o * CC + c) * KK2 + k2];
}

// ---------------- kernel 2: x[b][c][p] -> xT[b][g][p][cg] (tiled transpose) ----------------
__global__ void transpose_kernel(const float* __restrict__ x) {
    __shared__ float tile[32][33];
    int bg = blockIdx.z;                // b*4+g
    int c0 = blockIdx.y * 32;           // cg block
    int p0 = blockIdx.x * 32;           // pixel block
    int tx = threadIdx.x;               // 32
    int ty = threadIdx.y;               // 8
    const float* in = x + (size_t)bg * CG * HWP;
    float* out = g_xT + (size_t)bg * HWP * CG;
#pragma unroll
    for (int i = 0; i < 32; i += 8)
        tile[ty + i][tx] = in[(size_t)(c0 + ty + i) * HWP + p0 + tx];
    __syncthreads();
#pragma unroll
    for (int i = 0; i < 32; i += 8)
        out[(size_t)(p0 + ty + i) * CG + c0 + tx] = tile[tx][ty + i];
}

// ---------------- kernel 3: offsets (1x1 conv) + deformable im2col ----------------
// one warp per (b, g, p, k2); lanes cover the 64 group channels (2 reps of 32)
__global__ void im2col_kernel(const float* __restrict__ x_off,
                              const float* __restrict__ w_offset) {
    int tid = threadIdx.x;
    int lane = tid & 31;
    int wi = blockIdx.x * 8 + (tid >> 5);   // < 1,179,648
    int k2 = wi % KK2;
    int t = wi / KK2;
    int p = t & (HWP - 1);
    int t2 = t >> 12;
    int g = t2 & 3;
    int b = t2 >> 2;
    int h = p >> 6, w = p & 63;

    // offset = w_offset @ x_off  (channel j = (g*9+k2)*2 + {y,x})
    int j = (g * KK2 + k2) * 2;
    const float* xo = x_off + (size_t)b * 4 * HWP + p;
    float o0 = xo[0], o1 = xo[HWP], o2 = xo[2 * HWP], o3 = xo[3 * HWP];
    const float* wo = w_offset + (size_t)j * 4;
    float offy = wo[0] * o0 + wo[1] * o1 + wo[2] * o2 + wo[3] * o3;
    float offx = wo[4] * o0 + wo[5] * o1 + wo[6] * o2 + wo[7] * o3;

    float py = (float)(h + k2 / 3 - 1) + offy;
    float px = (float)(w + k2 % 3 - 1) + offx;
    float fy = floorf(py), fx = floorf(px);
    float wy = py - fy, wx = px - fx;
    int y0 = (int)fy, x0 = (int)fx;

    float w00 = (1.f - wy) * (1.f - wx);
    float w01 = (1.f - wy) * wx;
    float w10 = wy * (1.f - wx);
    float w11 = wy * wx;

    bool vy0 = (y0 >= 0) & (y0 < HH);
    bool vy1 = (y0 + 1 >= 0) & (y0 + 1 < HH);
    bool vx0 = (x0 >= 0) & (x0 < WW);
    bool vx1 = (x0 + 1 >= 0) & (x0 + 1 < WW);
    if (!(vy0 && vx0)) w00 = 0.f;
    if (!(vy0 && vx1)) w01 = 0.f;
    if (!(vy1 && vx0)) w10 = 0.f;
    if (!(vy1 && vx1)) w11 = 0.f;

    int y0c = min(max(y0, 0), HH - 1), y1c = min(max(y0 + 1, 0), HH - 1);
    int x0c = min(max(x0, 0), WW - 1), x1c = min(max(x0 + 1, 0), WW - 1);

    const float* base = g_xT + (size_t)(b * DGRP + g) * HWP * CG;
    const float* p00 = base + (size_t)(y0c * WW + x0c) * CG;
    const float* p01 = base + (size_t)(y0c * WW + x1c) * CG;
    const float* p10 = base + (size_t)(y1c * WW + x0c) * CG;
    const float* p11 = base + (size_t)(y1c * WW + x1c) * CG;

    float* dst = g_col + (size_t)(b * HWP + p) * CK + (g * KK2 + k2) * CG;
#pragma unroll
    for (int rep = 0; rep < 2; rep++) {
        int cg = lane + rep * 32;
        float v = w00 * p00[cg] + w01 * p01[cg] + w10 * p10[cg] + w11 * p11[cg];
        dst[cg] = v;
    }
}

// ---------------- kernel 4: SGEMM  y[b][p][o] = col[b][p][:] . wT[:][o] ----------------
// 128x128 block tile, BK=16, 8x8 microtiles, packed f32x2 FMA
__global__ __launch_bounds__(256, 2) void sgemm_kernel() {
    __shared__ float As[16][132];   // [kk][m], 132 pad: 16B-aligned rows, low STS conflicts
    __shared__ float Bs[16][128];   // [kk][n]
    int b = blockIdx.z;
    int m0 = blockIdx.y * 128;
    int n0 = blockIdx.x * 128;
    const float* A = g_col + (size_t)b * HWP * CK;
    float* Y = g_y + (size_t)b * HWP * OO;
    int tid = threadIdx.x;
    int tm = (tid >> 4) << 3;
    int tn = (tid & 15) << 3;

    unsigned long long acc[8][4];
#pragma unroll
    for (int i = 0; i < 8; i++)
#pragma unroll
        for (int jj = 0; jj < 4; jj++) acc[i][jj] = 0ull;

    for (int k0 = 0; k0 < CK; k0 += 16) {
        // A tile: 128 rows x 16 k, transposed into As[kk][m]
#pragma unroll
        for (int q = tid; q < 512; q += 256) {
            int r = q >> 2, c4 = (q & 3) << 2;
            float4 v = *(const float4*)(A + (size_t)(m0 + r) * CK + k0 + c4);
            As[c4 + 0][r] = v.x;
            As[c4 + 1][r] = v.y;
            As[c4 + 2][r] = v.z;
            As[c4 + 3][r] = v.w;
        }
        // B tile: 16 k-rows x 128 n
#pragma unroll
        for (int q = tid; q < 512; q += 256) {
            int kk = q >> 5, c4 = (q & 31) << 2;
            *(float4*)&Bs[kk][c4] =
                *(const float4*)(g_wT + (size_t)(k0 + kk) * OO + n0 + c4);
        }
        __syncthreads();
#pragma unroll
        for (int kk = 0; kk < 16; kk++) {
            float4 a0 = *(const float4*)&As[kk][tm];
            float4 a1 = *(const float4*)&As[kk][tm + 4];
            ulonglong2 b0 = *(const ulonglong2*)&Bs[kk][tn];
            ulonglong2 b1 = *(const ulonglong2*)&Bs[kk][tn + 4];
            unsigned long long bb[4] = {b0.x, b0.y, b1.x, b1.y};
            float av[8] = {a0.x, a0.y, a0.z, a0.w, a1.x, a1.y, a1.z, a1.w};
#pragma unroll
            for (int i = 0; i < 8; i++) {
                unsigned long long a2 = pack2(av[i]);
#pragma unroll
                for (int jj = 0; jj < 4; jj++) fma2(acc[i][jj], a2, bb[jj]);
            }
        }
        __syncthreads();
    }
    // epilogue: write y (NHWC)
#pragma unroll
    for (int i = 0; i < 8; i++) {
        float* row = Y + (size_t)(m0 + tm + i) * OO + n0 + tn;
        float4 v0, v1;
        unpack2(acc[i][0], v0.x, v0.y);
        unpack2(acc[i][1], v0.z, v0.w);
        unpack2(acc[i][2], v1.x, v1.y);
        unpack2(acc[i][3], v1.z, v1.w);
        *(float4*)(row) = v0;
        *(float4*)(row + 4) = v1;
    }
}

// ---------------- kernel 5: GroupNorm stats + normalize + ReLU + NHWC->NCHW ----------------
__global__ void gn_kernel(const float* __restrict__ gamma,
                          const float* __restrict__ beta, float* __restrict__ out) {
    int b = blockIdx.x >> 5;
    int gi = blockIdx.x & 31;
    int tid = threadIdx.x;   // 256
    const float* yb = g_y + (size_t)b * HWP * OO;

    float s = 0.f, ss = 0.f;
    for (int e4 = tid; e4 < 8192; e4 += 256) {   // 32768 elems / 4
        int p = e4 >> 1, j4 = e4 & 1;
        float4 v = *(const float4*)(yb + (size_t)p * OO + gi * 8 + j4 * 4);
        s += v.x + v.y + v.z + v.w;
        ss += v.x * v.x + v.y * v.y + v.z * v.z + v.w * v.w;
    }
    __shared__ float rs[256], rss[256];
    rs[tid] = s;
    rss[tid] = ss;
    __syncthreads();
    for (int st = 128; st > 0; st >>= 1) {
        if (tid < st) {
            rs[tid] += rs[tid + st];
            rss[tid] += rss[tid + st];
        }
        __syncthreads();
    }
    float mu = rs[0] * (1.f / 32768.f);
    float var = rss[0] * (1.f / 32768.f) - mu * mu;
    float rstd = rsqrtf(var + 1e-5f);

#pragma unroll
    for (int j = 0; j < 8; j++) {
        int o = gi * 8 + j;
        float ga = gamma[o] * rstd;
        float be = beta[o] - mu * ga;
        float* ob = out + (size_t)(b * OO + o) * HWP;
        for (int p = tid; p < HWP; p += 256) {
            float v = yb[(size_t)p * OO + o];
            ob[p] = fmaxf(fmaf(v, ga, be), 0.f);
        }
    }
}

// ---------------- launch ----------------
extern "C" void kernel_launch(void* const* d_in, const int* in_sizes, int n_in,
                              void* d_out, int out_size) {
    const float* x        = (const float*)d_in[0];
    const float* x_off    = (const float*)d_in[1];
    const float* w_offset = (const float*)d_in[2];
    const float* w_deform = (const float*)d_in[3];
    const float* gamma    = (const float*)d_in[4];
    const float* beta     = (const float*)d_in[5];
    float* out = (float*)d_out;

    wprep_kernel<<<CK * OO / 256, 256>>>(w_deform);

    dim3 tb(32, 8), tg(HWP / 32, CG / 32, BB * DGRP);
    transpose_kernel<<<tg, tb>>>(x);

    // warps = B*DG*HW*K2 = 1,179,648 ; 8 warps/block
    im2col_kernel<<<147456, 256>>>(x_off, w_offset);

    dim3 gg(OO / 128, HWP / 128, BB);
    sgemm_kernel<<<gg, 256>>>();

    gn_kernel<<<BB * 32, 256>>>(gamma, beta, out);
}

// round 4
// speedup vs baseline: 2.1445x; 2.1445x over previous
#include <cuda_runtime.h>
#include <cstdint>

#define BB 8
#define CC 256
#define OO 256
#define HH 64
#define WW 64
#define DGRP 4
#define CG 64
#define KK2 9
#define CK 2304      /* C*K2 */
#define HWP 4096     /* H*W */
#define MTOT (BB * HWP)   /* 32768 */

// ---------------- scratch (device globals; no cudaMalloc allowed) ----------------
__device__ __align__(256) float g_xT[(size_t)BB * DGRP * HWP * CG];   // 32 MB
__device__ __align__(256) float g_col[(size_t)MTOT * CK];             // 302 MB (tf32-rounded)
__device__ __align__(256) float g_wK[(size_t)OO * CK];                // 2.36 MB, [o][ck] K-major
__device__ __align__(256) float g_y[(size_t)MTOT * OO];               // 32 MB, conv out (NHWC)

// ---------------- helpers ----------------
__device__ __forceinline__ uint32_t smem_u32(const void* p) {
    uint32_t a;
    asm("{ .reg .u64 t; cvta.to.shared.u64 t, %1; cvt.u32.u64 %0, t; }" : "=r"(a) : "l"(p));
    return a;
}
__device__ __forceinline__ float to_tf32(float x) {
    uint32_t u;
    asm("cvt.rna.tf32.f32 %0, %1;" : "=r"(u) : "f"(x));
    return __uint_as_float(u);
}
__device__ __forceinline__ void cp16(uint32_t dst, const void* src) {
    asm volatile("cp.async.cg.shared.global [%0], [%1], 16;" :: "r"(dst), "l"(src));
}
__device__ __forceinline__ void mma_tf32(float* d, const uint32_t* a, const uint32_t* b) {
    asm volatile(
        "mma.sync.aligned.m16n8k8.row.col.f32.tf32.tf32.f32 "
        "{%0,%1,%2,%3}, {%4,%5,%6,%7}, {%8,%9}, {%0,%1,%2,%3};"
        : "+f"(d[0]), "+f"(d[1]), "+f"(d[2]), "+f"(d[3])
        : "r"(a[0]), "r"(a[1]), "r"(a[2]), "r"(a[3]), "r"(b[0]), "r"(b[1]));
}

// ---------------- kernel 1: weights -> g_wK[o][ck] (K-major, tf32-rounded) ----------------
__global__ void wprep_kernel(const float* __restrict__ wd) {
    int idx = blockIdx.x * 256 + threadIdx.x;   // < OO*CK
    int o = idx / CK;
    int ck = idx - o * CK;
    int cg = ck & 63;
    int t = ck >> 6;
    int k2 = t % KK2;
    int g = t / KK2;
    g_wK[idx] = to_tf32(wd[((size_t)o * CC + g * CG + cg) * KK2 + k2]);
}

// ---------------- kernel 2: x[b][c][p] -> xT[b][g][p][cg] ----------------
__global__ void transpose_kernel(const float* __restrict__ x) {
    __shared__ float tile[32][33];
    int bg = blockIdx.z;
    int c0 = blockIdx.y * 32;
    int p0 = blockIdx.x * 32;
    int tx = threadIdx.x, ty = threadIdx.y;
    const float* in = x + (size_t)bg * CG * HWP;
    float* out = g_xT + (size_t)bg * HWP * CG;
#pragma unroll
    for (int i = 0; i < 32; i += 8)
        tile[ty + i][tx] = in[(size_t)(c0 + ty + i) * HWP + p0 + tx];
    __syncthreads();
#pragma unroll
    for (int i = 0; i < 32; i += 8)
        out[(size_t)(p0 + ty + i) * CG + c0 + tx] = tile[tx][ty + i];
}

// ---------------- kernel 3: offsets (1x1 conv) + deformable im2col ----------------
__global__ void im2col_kernel(const float* __restrict__ x_off,
                              const float* __restrict__ w_offset) {
    int tid = threadIdx.x;
    int lane = tid & 31;
    int wi = blockIdx.x * 8 + (tid >> 5);
    int k2 = wi % KK2;
    int t = wi / KK2;
    int p = t & (HWP - 1);
    int t2 = t >> 12;
    int g = t2 & 3;
    int b = t2 >> 2;
    int h = p >> 6, w = p & 63;

    int j = (g * KK2 + k2) * 2;
    const float* xo = x_off + (size_t)b * 4 * HWP + p;
    float o0 = xo[0], o1 = xo[HWP], o2 = xo[2 * HWP], o3 = xo[3 * HWP];
    const float* wo = w_offset + (size_t)j * 4;
    float offy = wo[0] * o0 + wo[1] * o1 + wo[2] * o2 + wo[3] * o3;
    float offx = wo[4] * o0 + wo[5] * o1 + wo[6] * o2 + wo[7] * o3;

    float py = (float)(h + k2 / 3 - 1) + offy;
    float px = (float)(w + k2 % 3 - 1) + offx;
    float fy = floorf(py), fx = floorf(px);
    float wy = py - fy, wx = px - fx;
    int y0 = (int)fy, x0 = (int)fx;

    float w00 = (1.f - wy) * (1.f - wx);
    float w01 = (1.f - wy) * wx;
    float w10 = wy * (1.f - wx);
    float w11 = wy * wx;

    bool vy0 = (y0 >= 0) & (y0 < HH);
    bool vy1 = (y0 + 1 >= 0) & (y0 + 1 < HH);
    bool vx0 = (x0 >= 0) & (x0 < WW);
    bool vx1 = (x0 + 1 >= 0) & (x0 + 1 < WW);
    if (!(vy0 && vx0)) w00 = 0.f;
    if (!(vy0 && vx1)) w01 = 0.f;
    if (!(vy1 && vx0)) w10 = 0.f;
    if (!(vy1 && vx1)) w11 = 0.f;

    int y0c = min(max(y0, 0), HH - 1), y1c = min(max(y0 + 1, 0), HH - 1);
    int x0c = min(max(x0, 0), WW - 1), x1c = min(max(x0 + 1, 0), WW - 1);

    const float* base = g_xT + (size_t)(b * DGRP + g) * HWP * CG;
    const float* p00 = base + (size_t)(y0c * WW + x0c) * CG;
    const float* p01 = base + (size_t)(y0c * WW + x1c) * CG;
    const float* p10 = base + (size_t)(y1c * WW + x0c) * CG;
    const float* p11 = base + (size_t)(y1c * WW + x1c) * CG;

    float* dst = g_col + (size_t)(b * HWP + p) * CK + (g * KK2 + k2) * CG;
#pragma unroll
    for (int rep = 0; rep < 2; rep++) {
        int cg = lane + rep * 32;
        float v = w00 * p00[cg] + w01 * p01[cg] + w10 * p10[cg] + w11 * p11[cg];
        dst[cg] = to_tf32(v);
    }
}

// ---------------- kernel 4: tf32 mma.sync GEMM  y[m][o] = col[m][:] . wK[o][:] ----------------
// block 128x128, BK=16, 8 warps (2x4), warp tile 64x32, [row][20]-padded smem
#define BK 16
#define LDT 20
#define NST (CK / BK)   /* 144 */

__global__ __launch_bounds__(256, 2) void gemm_kernel() {
    __shared__ float As[2][128 * LDT];
    __shared__ float Bs[2][128 * LDT];
    int tid = threadIdx.x;
    int n0 = blockIdx.x * 128;
    int m0 = blockIdx.y * 128;
    uint32_t sA0 = smem_u32(&As[0][0]);
    uint32_t sB0 = smem_u32(&Bs[0][0]);

    int lane = tid & 31, w = tid >> 5;
    int wm = (w >> 2) * 64;   // warp m-offset (0/64)
    int wn = (w & 3) * 32;    // warp n-offset (0/32/64/96)
    int g = lane >> 2, tq = lane & 3;

    // copy task: thread handles (row, chunk) pairs; q in [0,512): row=q>>2, c4=q&3
    int r0 = tid >> 2, c40 = tid & 3;         // q = tid
    int r1 = (tid + 256) >> 2, c41 = tid & 3; // q = tid+256

    float acc[4][4][4];
#pragma unroll
    for (int i = 0; i < 4; i++)
#pragma unroll
        for (int jj = 0; jj < 4; jj++)
#pragma unroll
            for (int e = 0; e < 4; e++) acc[i][jj][e] = 0.f;

    // ---- prologue: stage 0 into buf 0 ----
    {
        int k0 = 0;
        cp16(sA0 + (uint32_t)(r0 * LDT + c40 * 4) * 4,
             g_col + (size_t)(m0 + r0) * CK + k0 + c40 * 4);
        cp16(sA0 + (uint32_t)(r1 * LDT + c41 * 4) * 4,
             g_col + (size_t)(m0 + r1) * CK + k0 + c41 * 4);
        cp16(sB0 + (uint32_t)(r0 * LDT + c40 * 4) * 4,
             g_wK + (size_t)(n0 + r0) * CK + k0 + c40 * 4);
        cp16(sB0 + (uint32_t)(r1 * LDT + c41 * 4) * 4,
             g_wK + (size_t)(n0 + r1) * CK + k0 + c41 * 4);
        asm volatile("cp.async.commit_group;" ::: "memory");
    }

    for (int s = 0; s < NST; s++) {
        int buf = s & 1;
        if (s + 1 < NST) {
            int nb = (s + 1) & 1;
            int k0 = (s + 1) * BK;
            uint32_t a_base = sA0 + (uint32_t)(nb * 128 * LDT * 4);
            uint32_t b_base = sB0 + (uint32_t)(nb * 128 * LDT * 4);
            cp16(a_base + (uint32_t)(r0 * LDT + c40 * 4) * 4,
                 g_col + (size_t)(m0 + r0) * CK + k0 + c40 * 4);
            cp16(a_base + (uint32_t)(r1 * LDT + c41 * 4) * 4,
                 g_col + (size_t)(m0 + r1) * CK + k0 + c41 * 4);
            cp16(b_base + (uint32_t)(r0 * LDT + c40 * 4) * 4,
                 g_wK + (size_t)(n0 + r0) * CK + k0 + c40 * 4);
            cp16(b_base + (uint32_t)(r1 * LDT + c41 * 4) * 4,
                 g_wK + (size_t)(n0 + r1) * CK + k0 + c41 * 4);
            asm volatile("cp.async.commit_group;" ::: "memory");
            asm volatile("cp.async.wait_group 1;" ::: "memory");
        } else {
            asm volatile("cp.async.wait_group 0;" ::: "memory");
        }
        __syncthreads();

        const float* A = &As[buf][0];
        const float* B = &Bs[buf][0];
#pragma unroll
        for (int ks = 0; ks < 2; ks++) {
            uint32_t af[4][4], bf[4][2];
#pragma unroll
            for (int i = 0; i < 4; i++) {
                const float* ap = A + (wm + i * 16 + g) * LDT + ks * 8 + tq;
                af[i][0] = __float_as_uint(ap[0]);
                af[i][1] = __float_as_uint(ap[8 * LDT]);
                af[i][2] = __float_as_uint(ap[4]);
                af[i][3] = __float_as_uint(ap[8 * LDT + 4]);
            }
#pragma unroll
            for (int jj = 0; jj < 4; jj++) {
                const float* bp = B + (wn + jj * 8 + g) * LDT + ks * 8 + tq;
                bf[jj][0] = __float_as_uint(bp[0]);
                bf[jj][1] = __float_as_uint(bp[4]);
            }
#pragma unroll
            for (int i = 0; i < 4; i++)
#pragma unroll
                for (int jj = 0; jj < 4; jj++) mma_tf32(acc[i][jj], af[i], bf[jj]);
        }
        __syncthreads();
    }

    // ---- epilogue: write y (NHWC rows of 256) ----
#pragma unroll
    for (int i = 0; i < 4; i++) {
#pragma unroll
        for (int jj = 0; jj < 4; jj++) {
            int row = m0 + wm + i * 16 + g;
            int col = n0 + wn + jj * 8 + 2 * tq;
            float2 v0 = make_float2(acc[i][jj][0], acc[i][jj][1]);
            float2 v1 = make_float2(acc[i][jj][2], acc[i][jj][3]);
            *(float2*)(g_y + (size_t)row * OO + col) = v0;
            *(float2*)(g_y + (size_t)(row + 8) * OO + col) = v1;
        }
    }
}

// ---------------- kernel 5: GroupNorm + ReLU + NHWC->NCHW (smem-staged) ----------------
__global__ void gn_kernel(const float* __restrict__ gamma,
                          const float* __restrict__ beta, float* __restrict__ out) {
    int b = blockIdx.x >> 5;
    int gi = blockIdx.x & 31;
    int tid = threadIdx.x;   // 256
    const float* yb = g_y + (size_t)b * HWP * OO;

    float s = 0.f, ss = 0.f;
    for (int e4 = tid; e4 < 8192; e4 += 256) {
        int p = e4 >> 1, j4 = e4 & 1;
        float4 v = *(const float4*)(yb + (size_t)p * OO + gi * 8 + j4 * 4);
        s += v.x + v.y + v.z + v.w;
        ss += v.x * v.x + v.y * v.y + v.z * v.z + v.w * v.w;
    }
    __shared__ float rs[256], rss[256];
    rs[tid] = s;
    rss[tid] = ss;
    __syncthreads();
    for (int st = 128; st > 0; st >>= 1) {
        if (tid < st) {
            rs[tid] += rs[tid + st];
            rss[tid] += rss[tid + st];
        }
        __syncthreads();
    }
    float mu = rs[0] * (1.f / 32768.f);
    float var = rss[0] * (1.f / 32768.f) - mu * mu;
    float rstd = rsqrtf(var + 1e-5f);

    float ga[8], be[8];
#pragma unroll
    for (int j = 0; j < 8; j++) {
        int o = gi * 8 + j;
        ga[j] = gamma[o] * rstd;
        be[j] = beta[o] - mu * ga[j];
    }

    __shared__ float stb[8 * 520];   // [ch][520]
    for (int p0 = 0; p0 < HWP; p0 += 512) {
#pragma unroll
        for (int q = 0; q < 2; q++) {
            int pp = tid * 2 + q;   // 0..511
            const float* src = yb + (size_t)(p0 + pp) * OO + gi * 8;
            float4 v0 = *(const float4*)src;
            float4 v1 = *(const float4*)(src + 4);
            float r[8] = {v0.x, v0.y, v0.z, v0.w, v1.x, v1.y, v1.z, v1.w};
#pragma unroll
            for (int j = 0; j < 8; j++)
                stb[j * 520 + pp] = fmaxf(fmaf(r[j], ga[j], be[j]), 0.f);
        }
        __syncthreads();
#pragma unroll
        for (int q = 0; q < 4; q++) {
            int idx = tid + q * 256;
            int ch = idx >> 7, p4 = (idx & 127) * 4;
            float4 v = *(float4*)&stb[ch * 520 + p4];
            *(float4*)(out + (size_t)(b * OO + gi * 8 + ch) * HWP + p0 + p4) = v;
        }
        __syncthreads();
    }
}

// ---------------- launch ----------------
extern "C" void kernel_launch(void* const* d_in, const int* in_sizes, int n_in,
                              void* d_out, int out_size) {
    const float* x        = (const float*)d_in[0];
    const float* x_off    = (const float*)d_in[1];
    const float* w_offset = (const float*)d_in[2];
    const float* w_deform = (const float*)d_in[3];
    const float* gamma    = (const float*)d_in[4];
    const float* beta     = (const float*)d_in[5];
    float* out = (float*)d_out;

    wprep_kernel<<<OO * CK / 256, 256>>>(w_deform);

    dim3 tb(32, 8), tg(HWP / 32, CG / 32, BB * DGRP);
    transpose_kernel<<<tg, tb>>>(x);

    im2col_kernel<<<147456, 256>>>(x_off, w_offset);

    dim3 gg(OO / 128, MTOT / 128);
    gemm_kernel<<<gg, 256>>>();

    gn_kernel<<<BB * 32, 256>>>(gamma, beta, out);
}

// round 5
// speedup vs baseline: 2.6196x; 1.2216x over previous
#include <cuda_runtime.h>
#include <cstdint>

#define BB 8
#define CC 256
#define OO 256
#define HH 64
#define WW 64
#define DGRP 4
#define CG 64
#define KK2 9
#define CK 2304      /* C*K2 */
#define HWP 4096     /* H*W */
#define MTOT (BB * HWP)   /* 32768 */

// ---------------- scratch (device globals; no cudaMalloc allowed) ----------------
__device__ __align__(256) float g_xT[(size_t)BB * DGRP * HWP * CG];   // 32 MB
__device__ __align__(256) float g_col[(size_t)MTOT * CK];             // 302 MB (tf32-rounded)
__device__ __align__(256) float g_wK[(size_t)OO * CK];                // 2.36 MB, [o][ck] K-major
__device__ __align__(256) float g_y[(size_t)MTOT * OO];               // 32 MB, conv out (NHWC)

// ---------------- helpers ----------------
__device__ __forceinline__ uint32_t smem_u32(const void* p) {
    uint32_t a;
    asm("{ .reg .u64 t; cvta.to.shared.u64 t, %1; cvt.u32.u64 %0, t; }" : "=r"(a) : "l"(p));
    return a;
}
__device__ __forceinline__ float to_tf32(float x) {
    uint32_t u;
    asm("cvt.rna.tf32.f32 %0, %1;" : "=r"(u) : "f"(x));
    return __uint_as_float(u);
}
__device__ __forceinline__ void cp16(uint32_t dst, const void* src) {
    asm volatile("cp.async.cg.shared.global [%0], [%1], 16;" :: "r"(dst), "l"(src));
}
__device__ __forceinline__ void mma_tf32(float* d, const uint32_t* a, const uint32_t* b) {
    asm volatile(
        "mma.sync.aligned.m16n8k8.row.col.f32.tf32.tf32.f32 "
        "{%0,%1,%2,%3}, {%4,%5,%6,%7}, {%8,%9}, {%0,%1,%2,%3};"
        : "+f"(d[0]), "+f"(d[1]), "+f"(d[2]), "+f"(d[3])
        : "r"(a[0]), "r"(a[1]), "r"(a[2]), "r"(a[3]), "r"(b[0]), "r"(b[1]));
}

// ---------------- kernel 1: weights -> g_wK[o][ck] (K-major, tf32-rounded) ----------------
__global__ void wprep_kernel(const float* __restrict__ wd) {
    int idx = blockIdx.x * 256 + threadIdx.x;   // < OO*CK
    int o = idx / CK;
    int ck = idx - o * CK;
    int cg = ck & 63;
    int t = ck >> 6;
    int k2 = t % KK2;
    int g = t / KK2;
    g_wK[idx] = to_tf32(wd[((size_t)o * CC + g * CG + cg) * KK2 + k2]);
}

// ---------------- kernel 2: x[b][c][p] -> xT[b][g][p][cg] ----------------
__global__ void transpose_kernel(const float* __restrict__ x) {
    __shared__ float tile[32][33];
    int bg = blockIdx.z;
    int c0 = blockIdx.y * 32;
    int p0 = blockIdx.x * 32;
    int tx = threadIdx.x, ty = threadIdx.y;
    const float* in = x + (size_t)bg * CG * HWP;
    float* out = g_xT + (size_t)bg * HWP * CG;
#pragma unroll
    for (int i = 0; i < 32; i += 8)
        tile[ty + i][tx] = in[(size_t)(c0 + ty + i) * HWP + p0 + tx];
    __syncthreads();
#pragma unroll
    for (int i = 0; i < 32; i += 8)
        out[(size_t)(p0 + ty + i) * CG + c0 + tx] = tile[tx][ty + i];
}

// ---------------- kernel 3: offsets (1x1 conv) + deformable im2col ----------------
// one warp per (b, g, p); handles all 9 kernel points
__global__ void im2col_kernel(const float* __restrict__ x_off,
                              const float* __restrict__ w_offset) {
    int tid = threadIdx.x;
    int lane = tid & 31;
    int wi = blockIdx.x * 8 + (tid >> 5);   // < 131072 = B*DG*HW
    int p = wi & (HWP - 1);
    int t2 = wi >> 12;
    int g = t2 & 3;
    int b = t2 >> 2;
    int h = p >> 6, w = p & 63;

    // broadcast the 4 x_off inputs for this pixel
    const float* xo = x_off + (size_t)b * 4 * HWP + p;
    float ov = (lane < 4) ? xo[(size_t)lane * HWP] : 0.f;
    float o0 = __shfl_sync(0xFFFFFFFFu, ov, 0);
    float o1 = __shfl_sync(0xFFFFFFFFu, ov, 1);
    float o2 = __shfl_sync(0xFFFFFFFFu, ov, 2);
    float o3 = __shfl_sync(0xFFFFFFFFu, ov, 3);

    // lanes 0..17 compute the 18 offset components (9 y then 9 x)
    float comp = 0.f;
    if (lane < 18) {
        int k2c = lane % 9;
        int ax = lane / 9;
        const float* wo = w_offset + (size_t)(((g * KK2 + k2c) * 2 + ax)) * 4;
        comp = wo[0] * o0 + wo[1] * o1 + wo[2] * o2 + wo[3] * o3;
    }

    const float* base = g_xT + (size_t)(b * DGRP + g) * HWP * CG;
    float* dstbase = g_col + (size_t)(b * HWP + p) * CK + g * KK2 * CG;

#pragma unroll
    for (int k2 = 0; k2 < KK2; k2++) {
        float offy = __shfl_sync(0xFFFFFFFFu, comp, k2);
        float offx = __shfl_sync(0xFFFFFFFFu, comp, k2 + 9);
        float py = (float)(h + k2 / 3 - 1) + offy;
        float px = (float)(w + k2 % 3 - 1) + offx;
        float fy = floorf(py), fx = floorf(px);
        float wy = py - fy, wx = px - fx;
        int y0 = (int)fy, x0 = (int)fx;

        float w00 = (1.f - wy) * (1.f - wx);
        float w01 = (1.f - wy) * wx;
        float w10 = wy * (1.f - wx);
        float w11 = wy * wx;

        bool vy0 = (y0 >= 0) & (y0 < HH);
        bool vy1 = (y0 + 1 >= 0) & (y0 + 1 < HH);
        bool vx0 = (x0 >= 0) & (x0 < WW);
        bool vx1 = (x0 + 1 >= 0) & (x0 + 1 < WW);
        if (!(vy0 && vx0)) w00 = 0.f;
        if (!(vy0 && vx1)) w01 = 0.f;
        if (!(vy1 && vx0)) w10 = 0.f;
        if (!(vy1 && vx1)) w11 = 0.f;

        int y0c = min(max(y0, 0), HH - 1), y1c = min(max(y0 + 1, 0), HH - 1);
        int x0c = min(max(x0, 0), WW - 1), x1c = min(max(x0 + 1, 0), WW - 1);

        const float* p00 = base + (size_t)(y0c * WW + x0c) * CG;
        const float* p01 = base + (size_t)(y0c * WW + x1c) * CG;
        const float* p10 = base + (size_t)(y1c * WW + x0c) * CG;
        const float* p11 = base + (size_t)(y1c * WW + x1c) * CG;

        float* dst = dstbase + k2 * CG;
#pragma unroll
        for (int rep = 0; rep < 2; rep++) {
            int cg = lane + rep * 32;
            float v = w00 * p00[cg] + w01 * p01[cg] + w10 * p10[cg] + w11 * p11[cg];
            dst[cg] = to_tf32(v);
        }
    }
}

// ---------------- kernel 4: tf32 mma.sync GEMM  y[m][o] = col[m][:] . wK[o][:] ----------------
// block 128x128, BK=16, 8 warps (2x4), warp tile 64x32, [row][20]-padded smem
// 3-stage cp.async ring, single __syncthreads per K-step
#define BK 16
#define LDT 20
#define NST (CK / BK)   /* 144 */
#define NSTAGE 3
#define STG_F (128 * LDT)                 /* floats per A (or B) stage */
#define GEMM_SMEM (NSTAGE * 2 * STG_F * 4)

__global__ __launch_bounds__(256, 2) void gemm_kernel() {
    extern __shared__ __align__(16) float dsm[];
    float* Asm = dsm;                       // NSTAGE stages of A
    float* Bsm = dsm + NSTAGE * STG_F;      // NSTAGE stages of B
    uint32_t sA0 = smem_u32(Asm);
    uint32_t sB0 = smem_u32(Bsm);

    int tid = threadIdx.x;
    int n0 = blockIdx.x * 128;
    int m0 = blockIdx.y * 128;

    int lane = tid & 31, w = tid >> 5;
    int wm = (w >> 2) * 64;   // warp m-offset (0/64)
    int wn = (w & 3) * 32;    // warp n-offset (0/32/64/96)
    int g = lane >> 2, tq = lane & 3;

    int r0 = tid >> 2, c40 = tid & 3;
    int r1 = (tid + 256) >> 2, c41 = tid & 3;

    float acc[4][4][4];
#pragma unroll
    for (int i = 0; i < 4; i++)
#pragma unroll
        for (int jj = 0; jj < 4; jj++)
#pragma unroll
            for (int e = 0; e < 4; e++) acc[i][jj][e] = 0.f;

    // ---- prologue: issue stages 0 and 1, one commit group each ----
#pragma unroll
    for (int s = 0; s < NSTAGE - 1; s++) {
        int k0 = s * BK;
        uint32_t a_base = sA0 + (uint32_t)(s * STG_F * 4);
        uint32_t b_base = sB0 + (uint32_t)(s * STG_F * 4);
        cp16(a_base + (uint32_t)(r0 * LDT + c40 * 4) * 4,
             g_col + (size_t)(m0 + r0) * CK + k0 + c40 * 4);
        cp16(a_base + (uint32_t)(r1 * LDT + c41 * 4) * 4,
             g_col + (size_t)(m0 + r1) * CK + k0 + c41 * 4);
        cp16(b_base + (uint32_t)(r0 * LDT + c40 * 4) * 4,
             g_wK + (size_t)(n0 + r0) * CK + k0 + c40 * 4);
        cp16(b_base + (uint32_t)(r1 * LDT + c41 * 4) * 4,
             g_wK + (size_t)(n0 + r1) * CK + k0 + c41 * 4);
        asm volatile("cp.async.commit_group;" ::: "memory");
    }

    int buf = 0;
    for (int s = 0; s < NST; s++) {
        // stage s must have arrived: outstanding groups are {s, s+1} here
        if (s + 1 < NST) {
            asm volatile("cp.async.wait_group 1;" ::: "memory");
        } else {
            asm volatile("cp.async.wait_group 0;" ::: "memory");
        }
        __syncthreads();

        // issue stage s+2 into buffer (s+2)%3 == (buf+2)%3 — safe: everyone
        // passed the barrier ending compute of stage s-1 (its old contents)
        if (s + 2 < NST) {
            int nb = buf + 2 >= NSTAGE ? buf + 2 - NSTAGE : buf + 2;
            int k0 = (s + 2) * BK;
            uint32_t a_base = sA0 + (uint32_t)(nb * STG_F * 4);
            uint32_t b_base = sB0 + (uint32_t)(nb * STG_F * 4);
            cp16(a_base + (uint32_t)(r0 * LDT + c40 * 4) * 4,
                 g_col + (size_t)(m0 + r0) * CK + k0 + c40 * 4);
            cp16(a_base + (uint32_t)(r1 * LDT + c41 * 4) * 4,
                 g_col + (size_t)(m0 + r1) * CK + k0 + c41 * 4);
            cp16(b_base + (uint32_t)(r0 * LDT + c40 * 4) * 4,
                 g_wK + (size_t)(n0 + r0) * CK + k0 + c40 * 4);
            cp16(b_base + (uint32_t)(r1 * LDT + c41 * 4) * 4,
                 g_wK + (size_t)(n0 + r1) * CK + k0 + c41 * 4);
            asm volatile("cp.async.commit_group;" ::: "memory");
        }

        const float* A = Asm + buf * STG_F;
        const float* B = Bsm + buf * STG_F;
#pragma unroll
        for (int ks = 0; ks < 2; ks++) {
            uint32_t af[4][4], bf[4][2];
#pragma unroll
            for (int i = 0; i < 4; i++) {
                const float* ap = A + (wm + i * 16 + g) * LDT + ks * 8 + tq;
                af[i][0] = __float_as_uint(ap[0]);
                af[i][1] = __float_as_uint(ap[8 * LDT]);
                af[i][2] = __float_as_uint(ap[4]);
                af[i][3] = __float_as_uint(ap[8 * LDT + 4]);
            }
#pragma unroll
            for (int jj = 0; jj < 4; jj++) {
                const float* bp = B + (wn + jj * 8 + g) * LDT + ks * 8 + tq;
                bf[jj][0] = __float_as_uint(bp[0]);
                bf[jj][1] = __float_as_uint(bp[4]);
            }
#pragma unroll
            for (int i = 0; i < 4; i++)
#pragma unroll
                for (int jj = 0; jj < 4; jj++) mma_tf32(acc[i][jj], af[i], bf[jj]);
        }

        buf = buf + 1 >= NSTAGE ? 0 : buf + 1;
    }

    // ---- epilogue: write y (NHWC rows of 256) ----
#pragma unroll
    for (int i = 0; i < 4; i++) {
#pragma unroll
        for (int jj = 0; jj < 4; jj++) {
            int row = m0 + wm + i * 16 + g;
            int col = n0 + wn + jj * 8 + 2 * tq;
            float2 v0 = make_float2(acc[i][jj][0], acc[i][jj][1]);
            float2 v1 = make_float2(acc[i][jj][2], acc[i][jj][3]);
            *(float2*)(g_y + (size_t)row * OO + col) = v0;
            *(float2*)(g_y + (size_t)(row + 8) * OO + col) = v1;
        }
    }
}

// ---------------- kernel 5: GroupNorm + ReLU + NHWC->NCHW (smem-staged) ----------------
__global__ void gn_kernel(const float* __restrict__ gamma,
                          const float* __restrict__ beta, float* __restrict__ out) {
    int b = blockIdx.x >> 5;
    int gi = blockIdx.x & 31;
    int tid = threadIdx.x;   // 256
    const float* yb = g_y + (size_t)b * HWP * OO;

    float s = 0.f, ss = 0.f;
    for (int e4 = tid; e4 < 8192; e4 += 256) {
        int p = e4 >> 1, j4 = e4 & 1;
        float4 v = *(const float4*)(yb + (size_t)p * OO + gi * 8 + j4 * 4);
        s += v.x + v.y + v.z + v.w;
        ss += v.x * v.x + v.y * v.y + v.z * v.z + v.w * v.w;
    }
    __shared__ float rs[256], rss[256];
    rs[tid] = s;
    rss[tid] = ss;
    __syncthreads();
    for (int st = 128; st > 0; st >>= 1) {
        if (tid < st) {
            rs[tid] += rs[tid + st];
            rss[tid] += rss[tid + st];
        }
        __syncthreads();
    }
    float mu = rs[0] * (1.f / 32768.f);
    float var = rss[0] * (1.f / 32768.f) - mu * mu;
    float rstd = rsqrtf(var + 1e-5f);

    float ga[8], be[8];
#pragma unroll
    for (int j = 0; j < 8; j++) {
        int o = gi * 8 + j;
        ga[j] = gamma[o] * rstd;
        be[j] = beta[o] - mu * ga[j];
    }

    __shared__ float stb[8 * 520];   // [ch][520]
    for (int p0 = 0; p0 < HWP; p0 += 512) {
#pragma unroll
        for (int q = 0; q < 2; q++) {
            int pp = tid * 2 + q;   // 0..511
            const float* src = yb + (size_t)(p0 + pp) * OO + gi * 8;
            float4 v0 = *(const float4*)src;
            float4 v1 = *(const float4*)(src + 4);
            float r[8] = {v0.x, v0.y, v0.z, v0.w, v1.x, v1.y, v1.z, v1.w};
#pragma unroll
            for (int j = 0; j < 8; j++)
                stb[j * 520 + pp] = fmaxf(fmaf(r[j], ga[j], be[j]), 0.f);
        }
        __syncthreads();
#pragma unroll
        for (int q = 0; q < 4; q++) {
            int idx = tid + q * 256;
            int ch = idx >> 7, p4 = (idx & 127) * 4;
            float4 v = *(float4*)&stb[ch * 520 + p4];
            *(float4*)(out + (size_t)(b * OO + gi * 8 + ch) * HWP + p0 + p4) = v;
        }
        __syncthreads();
    }
}

// ---------------- launch ----------------
extern "C" void kernel_launch(void* const* d_in, const int* in_sizes, int n_in,
                              void* d_out, int out_size) {
    const float* x        = (const float*)d_in[0];
    const float* x_off    = (const float*)d_in[1];
    const float* w_offset = (const float*)d_in[2];
    const float* w_deform = (const float*)d_in[3];
    const float* gamma    = (const float*)d_in[4];
    const float* beta     = (const float*)d_in[5];
    float* out = (float*)d_out;

    cudaFuncSetAttribute(gemm_kernel, cudaFuncAttributeMaxDynamicSharedMemorySize,
                         GEMM_SMEM);

    wprep_kernel<<<OO * CK / 256, 256>>>(w_deform);

    dim3 tb(32, 8), tg(HWP / 32, CG / 32, BB * DGRP);
    transpose_kernel<<<tg, tb>>>(x);

    // warps = B*DG*HW = 131072 ; 8 warps/block
    im2col_kernel<<<16384, 256>>>(x_off, w_offset);

    dim3 gg(OO / 128, MTOT / 128);
    gemm_kernel<<<gg, 256, GEMM_SMEM>>>();

    gn_kernel<<<BB * 32, 256>>>(gamma, beta, out);
}

// round 7
// speedup vs baseline: 3.0743x; 1.1736x over previous
#include <cuda_runtime.h>
#include <cstdint>

#define BB 8
#define CC 256
#define OO 256
#define HH 64
#define WW 64
#define DGRP 4
#define CG 64
#define KK2 9
#define CK 2304      /* C*K2 */
#define HWP 4096     /* H*W */
#define MTOT (BB * HWP)   /* 32768 */

// ---------------- scratch (device globals; no cudaMalloc allowed) ----------------
__device__ __align__(256) float g_xT[(size_t)BB * DGRP * HWP * CG];   // 32 MB
__device__ __align__(256) float g_col[(size_t)MTOT * CK];             // 302 MB (tf32-rounded)
__device__ __align__(256) float g_wK[(size_t)OO * CK];                // 2.36 MB, [o][ck] K-major
__device__ __align__(256) float g_y[(size_t)MTOT * OO];               // 32 MB, conv out (NHWC)

// ---------------- helpers ----------------
__device__ __forceinline__ uint32_t smem_u32(const void* p) {
    uint32_t a;
    asm("{ .reg .u64 t; cvta.to.shared.u64 t, %1; cvt.u32.u64 %0, t; }" : "=r"(a) : "l"(p));
    return a;
}
__device__ __forceinline__ float to_tf32(float x) {
    uint32_t u;
    asm("cvt.rna.tf32.f32 %0, %1;" : "=r"(u) : "f"(x));
    return __uint_as_float(u);
}
__device__ __forceinline__ void cp16(uint32_t dst, const void* src) {
    asm volatile("cp.async.cg.shared.global [%0], [%1], 16;" :: "r"(dst), "l"(src));
}
__device__ __forceinline__ void ldsm4(uint32_t& r0, uint32_t& r1, uint32_t& r2,
                                      uint32_t& r3, uint32_t addr) {
    asm volatile("ldmatrix.sync.aligned.m8n8.x4.shared.b16 {%0,%1,%2,%3}, [%4];"
                 : "=r"(r0), "=r"(r1), "=r"(r2), "=r"(r3) : "r"(addr));
}
__device__ __forceinline__ void mma_tf32(float* d, const uint32_t* a, const uint32_t* b) {
    asm volatile(
        "mma.sync.aligned.m16n8k8.row.col.f32.tf32.tf32.f32 "
        "{%0,%1,%2,%3}, {%4,%5,%6,%7}, {%8,%9}, {%0,%1,%2,%3};"
        : "+f"(d[0]), "+f"(d[1]), "+f"(d[2]), "+f"(d[3])
        : "r"(a[0]), "r"(a[1]), "r"(a[2]), "r"(a[3]), "r"(b[0]), "r"(b[1]));
}

// ---------------- kernel 1: weights -> g_wK[o][ck] (K-major, tf32-rounded) ----------------
__global__ void wprep_kernel(const float* __restrict__ wd) {
    int idx = blockIdx.x * 256 + threadIdx.x;   // < OO*CK
    int o = idx / CK;
    int ck = idx - o * CK;
    int cg = ck & 63;
    int t = ck >> 6;
    int k2 = t % KK2;
    int g = t / KK2;
    g_wK[idx] = to_tf32(wd[((size_t)o * CC + g * CG + cg) * KK2 + k2]);
}

// ---------------- kernel 2: x[b][c][p] -> xT[b][g][p][cg] ----------------
__global__ void transpose_kernel(const float* __restrict__ x) {
    __shared__ float tile[32][33];
    int bg = blockIdx.z;
    int c0 = blockIdx.y * 32;
    int p0 = blockIdx.x * 32;
    int tx = threadIdx.x, ty = threadIdx.y;
    const float* in = x + (size_t)bg * CG * HWP;
    float* out = g_xT + (size_t)bg * HWP * CG;
#pragma unroll
    for (int i = 0; i < 32; i += 8)
        tile[ty + i][tx] = in[(size_t)(c0 + ty + i) * HWP + p0 + tx];
    __syncthreads();
#pragma unroll
    for (int i = 0; i < 32; i += 8)
        out[(size_t)(p0 + ty + i) * CG + c0 + tx] = tile[tx][ty + i];
}

// ---------------- kernel 3: offsets (1x1 conv) + deformable im2col ----------------
// one warp per (b, g, p); handles all 9 kernel points
__global__ void im2col_kernel(const float* __restrict__ x_off,
                              const float* __restrict__ w_offset) {
    int tid = threadIdx.x;
    int lane = tid & 31;
    int wi = blockIdx.x * 8 + (tid >> 5);   // < 131072 = B*DG*HW
    int p = wi & (HWP - 1);
    int t2 = wi >> 12;
    int g = t2 & 3;
    int b = t2 >> 2;
    int h = p >> 6, w = p & 63;

    const float* xo = x_off + (size_t)b * 4 * HWP + p;
    float ov = (lane < 4) ? xo[(size_t)lane * HWP] : 0.f;
    float o0 = __shfl_sync(0xFFFFFFFFu, ov, 0);
    float o1 = __shfl_sync(0xFFFFFFFFu, ov, 1);
    float o2 = __shfl_sync(0xFFFFFFFFu, ov, 2);
    float o3 = __shfl_sync(0xFFFFFFFFu, ov, 3);

    float comp = 0.f;
    if (lane < 18) {
        int k2c = lane % 9;
        int ax = lane / 9;
        const float* wo = w_offset + (size_t)(((g * KK2 + k2c) * 2 + ax)) * 4;
        comp = wo[0] * o0 + wo[1] * o1 + wo[2] * o2 + wo[3] * o3;
    }

    const float* base = g_xT + (size_t)(b * DGRP + g) * HWP * CG;
    float* dstbase = g_col + (size_t)(b * HWP + p) * CK + g * KK2 * CG;

#pragma unroll
    for (int k2 = 0; k2 < KK2; k2++) {
        float offy = __shfl_sync(0xFFFFFFFFu, comp, k2);
        float offx = __shfl_sync(0xFFFFFFFFu, comp, k2 + 9);
        float py = (float)(h + k2 / 3 - 1) + offy;
        float px = (float)(w + k2 % 3 - 1) + offx;
        float fy = floorf(py), fx = floorf(px);
        float wy = py - fy, wx = px - fx;
        int y0 = (int)fy, x0 = (int)fx;

        float w00 = (1.f - wy) * (1.f - wx);
        float w01 = (1.f - wy) * wx;
        float w10 = wy * (1.f - wx);
        float w11 = wy * wx;

        bool vy0 = (y0 >= 0) & (y0 < HH);
        bool vy1 = (y0 + 1 >= 0) & (y0 + 1 < HH);
        bool vx0 = (x0 >= 0) & (x0 < WW);
        bool vx1 = (x0 + 1 >= 0) & (x0 + 1 < WW);
        if (!(vy0 && vx0)) w00 = 0.f;
        if (!(vy0 && vx1)) w01 = 0.f;
        if (!(vy1 && vx0)) w10 = 0.f;
        if (!(vy1 && vx1)) w11 = 0.f;

        int y0c = min(max(y0, 0), HH - 1), y1c = min(max(y0 + 1, 0), HH - 1);
        int x0c = min(max(x0, 0), WW - 1), x1c = min(max(x0 + 1, 0), WW - 1);

        const float* p00 = base + (size_t)(y0c * WW + x0c) * CG;
        const float* p01 = base + (size_t)(y0c * WW + x1c) * CG;
        const float* p10 = base + (size_t)(y1c * WW + x0c) * CG;
        const float* p11 = base + (size_t)(y1c * WW + x1c) * CG;

        float* dst = dstbase + k2 * CG;
#pragma unroll
        for (int rep = 0; rep < 2; rep++) {
            int cg = lane + rep * 32;
            float v = w00 * p00[cg] + w01 * p01[cg] + w10 * p10[cg] + w11 * p11[cg];
            dst[cg] = to_tf32(v);
        }
    }
}

// ---------------- kernel 4: tf32 mma.sync GEMM  y[m][o] = col[m][:] . wK[o][:] ----------------
// block 128x128, BK=32, 8 warps (2x4), warp tile 64x32
// ldmatrix.x4 fragment loads, 3-stage cp.async ring, one barrier per K-step
#define BK 32
#define LDT 36
#define NST (CK / BK)   /* 72 */
#define NSTAGE 3
#define STG_F (128 * LDT)                 /* floats per A (or B) stage */
#define GEMM_SMEM (NSTAGE * 2 * STG_F * 4)   /* 110592 B */

__global__ __launch_bounds__(256, 2) void gemm_kernel() {
    extern __shared__ __align__(16) float dsm[];
    float* Asm = dsm;
    float* Bsm = dsm + NSTAGE * STG_F;
    uint32_t sA0 = smem_u32(Asm);
    uint32_t sB0 = smem_u32(Bsm);

    int tid = threadIdx.x;
    int n0 = blockIdx.x * 128;
    int m0 = blockIdx.y * 128;

    int lane = tid & 31, w = tid >> 5;
    int wm = (w >> 2) * 64;   // warp m-offset (0/64)
    int wn = (w & 3) * 32;    // warp n-offset (0/32/64/96)
    int g = lane >> 2, tq = lane & 3;

    // ldmatrix per-lane source offsets (floats)
    int sector = lane >> 3, rowin = lane & 7;
    int aoff[4], boff[2];
#pragma unroll
    for (int i = 0; i < 4; i++)
        aoff[i] = (wm + i * 16 + (sector & 1) * 8 + rowin) * LDT + (sector >> 1) * 4;
#pragma unroll
    for (int jp = 0; jp < 2; jp++)
        boff[jp] = (wn + (jp * 2 + (sector >> 1)) * 8 + rowin) * LDT + (sector & 1) * 4;

    // cp.async tasks: tile = 128 rows x 8 chunks(16B); thread handles 4 of 1024
    int cr[4], cc[4];
#pragma unroll
    for (int q = 0; q < 4; q++) {
        int task = tid + q * 256;
        cr[q] = task >> 3;
        cc[q] = (task & 7) * 4;
    }

    float acc[4][4][4];
#pragma unroll
    for (int i = 0; i < 4; i++)
#pragma unroll
        for (int jj = 0; jj < 4; jj++)
#pragma unroll
            for (int e = 0; e < 4; e++) acc[i][jj][e] = 0.f;

    // ---- prologue: stages 0,1 ----
#pragma unroll
    for (int s = 0; s < NSTAGE - 1; s++) {
        int k0 = s * BK;
        uint32_t a_base = sA0 + (uint32_t)(s * STG_F * 4);
        uint32_t b_base = sB0 + (uint32_t)(s * STG_F * 4);
#pragma unroll
        for (int q = 0; q < 4; q++) {
            cp16(a_base + (uint32_t)(cr[q] * LDT + cc[q]) * 4,
                 g_col + (size_t)(m0 + cr[q]) * CK + k0 + cc[q]);
            cp16(b_base + (uint32_t)(cr[q] * LDT + cc[q]) * 4,
                 g_wK + (size_t)(n0 + cr[q]) * CK + k0 + cc[q]);
        }
        asm volatile("cp.async.commit_group;" ::: "memory");
    }

    int buf = 0;
    for (int s = 0; s < NST; s++) {
        if (s + 1 < NST) {
            asm volatile("cp.async.wait_group 1;" ::: "memory");
        } else {
            asm volatile("cp.async.wait_group 0;" ::: "memory");
        }
        __syncthreads();

        if (s + 2 < NST) {
            int nb = buf + 2 >= NSTAGE ? buf + 2 - NSTAGE : buf + 2;
            int k0 = (s + 2) * BK;
            uint32_t a_base = sA0 + (uint32_t)(nb * STG_F * 4);
            uint32_t b_base = sB0 + (uint32_t)(nb * STG_F * 4);
#pragma unroll
            for (int q = 0; q < 4; q++) {
                cp16(a_base + (uint32_t)(cr[q] * LDT + cc[q]) * 4,
                     g_col + (size_t)(m0 + cr[q]) * CK + k0 + cc[q]);
                cp16(b_base + (uint32_t)(cr[q] * LDT + cc[q]) * 4,
                     g_wK + (size_t)(n0 + cr[q]) * CK + k0 + cc[q]);
            }
            asm volatile("cp.async.commit_group;" ::: "memory");
        }

        uint32_t abuf = sA0 + (uint32_t)(buf * STG_F * 4);
        uint32_t bbuf = sB0 + (uint32_t)(buf * STG_F * 4);
#pragma unroll
        for (int ks = 0; ks < 4; ks++) {
            uint32_t af[4][4], bf[4][2];
            uint32_t kofs = (uint32_t)(ks * 8) * 4;
#pragma unroll
            for (int i = 0; i < 4; i++)
                ldsm4(af[i][0], af[i][1], af[i][2], af[i][3],
                      abuf + kofs + (uint32_t)aoff[i] * 4);
            ldsm4(bf[0][0], bf[0][1], bf[1][0], bf[1][1],
                  bbuf + kofs + (uint32_t)boff[0] * 4);
            ldsm4(bf[2][0], bf[2][1], bf[3][0], bf[3][1],
                  bbuf + kofs + (uint32_t)boff[1] * 4);
#pragma unroll
            for (int i = 0; i < 4; i++)
#pragma unroll
                for (int jj = 0; jj < 4; jj++) mma_tf32(acc[i][jj], af[i], bf[jj]);
        }

        buf = buf + 1 >= NSTAGE ? 0 : buf + 1;
    }

    // ---- epilogue: write y (NHWC rows of 256) ----
#pragma unroll
    for (int i = 0; i < 4; i++) {
#pragma unroll
        for (int jj = 0; jj < 4; jj++) {
            int row = m0 + wm + i * 16 + g;
            int col = n0 + wn + jj * 8 + 2 * tq;
            float2 v0 = make_float2(acc[i][jj][0], acc[i][jj][1]);
            float2 v1 = make_float2(acc[i][jj][2], acc[i][jj][3]);
            *(float2*)(g_y + (size_t)row * OO + col) = v0;
            *(float2*)(g_y + (size_t)(row + 8) * OO + col) = v1;
        }
    }
}

// ---------------- kernel 5: GroupNorm + ReLU + NHWC->NCHW (smem-staged) ----------------
__global__ void gn_kernel(const float* __restrict__ gamma,
                          const float* __restrict__ beta, float* __restrict__ out) {
    int b = blockIdx.x >> 5;
    int gi = blockIdx.x & 31;
    int tid = threadIdx.x;   // 256
    const float* yb = g_y + (size_t)b * HWP * OO;

    float s = 0.f, ss = 0.f;
    for (int e4 = tid; e4 < 8192; e4 += 256) {
        int p = e4 >> 1, j4 = e4 & 1;
        float4 v = *(const float4*)(yb + (size_t)p * OO + gi * 8 + j4 * 4);
        s += v.x + v.y + v.z + v.w;
        ss += v.x * v.x + v.y * v.y + v.z * v.z + v.w * v.w;
    }
    __shared__ float rs[256], rss[256];
    rs[tid] = s;
    rss[tid] = ss;
    __syncthreads();
    for (int st = 128; st > 0; st >>= 1) {
        if (tid < st) {
            rs[tid] += rs[tid + st];
            rss[tid] += rss[tid + st];
        }
        __syncthreads();
    }
    float mu = rs[0] * (1.f / 32768.f);
    float var = rss[0] * (1.f / 32768.f) - mu * mu;
    float rstd = rsqrtf(var + 1e-5f);

    float ga[8], be[8];
#pragma unroll
    for (int j = 0; j < 8; j++) {
        int o = gi * 8 + j;
        ga[j] = gamma[o] * rstd;
        be[j] = beta[o] - mu * ga[j];
    }

    __shared__ float stb[8 * 520];   // [ch][520]
    for (int p0 = 0; p0 < HWP; p0 += 512) {
#pragma unroll
        for (int q = 0; q < 2; q++) {
            int pp = tid * 2 + q;   // 0..511
            const float* src = yb + (size_t)(p0 + pp) * OO + gi * 8;
            float4 v0 = *(const float4*)src;
            float4 v1 = *(const float4*)(src + 4);
            float r[8] = {v0.x, v0.y, v0.z, v0.w, v1.x, v1.y, v1.z, v1.w};
#pragma unroll
            for (int j = 0; j < 8; j++)
                stb[j * 520 + pp] = fmaxf(fmaf(r[j], ga[j], be[j]), 0.f);
        }
        __syncthreads();
#pragma unroll
        for (int q = 0; q < 4; q++) {
            int idx = tid + q * 256;
            int ch = idx >> 7, p4 = (idx & 127) * 4;
            float4 v = *(float4*)&stb[ch * 520 + p4];
            *(float4*)(out + (size_t)(b * OO + gi * 8 + ch) * HWP + p0 + p4) = v;
        }
        __syncthreads();
    }
}

// ---------------- launch ----------------
extern "C" void kernel_launch(void* const* d_in, const int* in_sizes, int n_in,
                              void* d_out, int out_size) {
    const float* x        = (const float*)d_in[0];
    const float* x_off    = (const float*)d_in[1];
    const float* w_offset = (const float*)d_in[2];
    const float* w_deform = (const float*)d_in[3];
    const float* gamma    = (const float*)d_in[4];
    const float* beta     = (const float*)d_in[5];
    float* out = (float*)d_out;

    cudaFuncSetAttribute(gemm_kernel, cudaFuncAttributeMaxDynamicSharedMemorySize,
                         GEMM_SMEM);

    wprep_kernel<<<OO * CK / 256, 256>>>(w_deform);

    dim3 tb(32, 8), tg(HWP / 32, CG / 32, BB * DGRP);
    transpose_kernel<<<tg, tb>>>(x);

    im2col_kernel<<<16384, 256>>>(x_off, w_offset);

    dim3 gg(OO / 128, MTOT / 128);
    gemm_kernel<<<gg, 256, GEMM_SMEM>>>();

    gn_kernel<<<BB * 32, 256>>>(gamma, beta, out);
}